// round 4
// baseline (speedup 1.0000x reference)
#include <cuda_runtime.h>

// Problem shape (fixed by dataset): B=4, H=16, S=2048, D=64, fp32.
#define BATCH 4
#define HEADS 16
#define SEQ   2048
#define DH    64

// Tiling: CTA = 128 query rows x full D; KV tiles of 128 keys.
#define BM 128
#define BN 128
#define NT 256            // threads per CTA (16 x 16)
#define SQ (BM + 4)       // stride for Qs/Ks, [d][row] layout (132 floats, 16B-mult)
#define SP (BM + 4)       // stride for Ps, [k][row] layout
#define SV (DH + 4)       // stride for Vs, [k][d] layout (68 floats, 16B-mult)

typedef unsigned long long ull;

// Packed fp32x2 ops (sm_103a FFMA2 path — only reachable via PTX, ptxas won't fuse).
#define FMA2(d, a, b, c) \
    asm("fma.rn.f32x2 %0, %1, %2, %3;" : "=l"(d) : "l"(a), "l"(b), "l"(c))
#define ADD2(d, a, b) \
    asm("add.rn.f32x2 %0, %1, %2;" : "=l"(d) : "l"(a), "l"(b))
#define MUL2(d, a, b) \
    asm("mul.rn.f32x2 %0, %1, %2;" : "=l"(d) : "l"(a), "l"(b))
#define PACKDUP(d, x) \
    asm("mov.b64 %0, {%1, %1};" : "=l"(d) : "f"(x))
#define PACK2(d, x, y) \
    asm("mov.b64 %0, {%1, %2};" : "=l"(d) : "f"(x), "f"(y))
#define UNPACK2(x, y, d) \
    asm("mov.b64 {%0, %1}, %2;" : "=f"(x), "=f"(y) : "l"(d))

struct SmemT {
    float Qs[DH][SQ];     // Q^T, pre-scaled by 1/sqrt(D)
    float Ks[DH][SQ];     // K^T for current tile
    float Vs[BN][SV];     // V  for current tile
    float Ps[BN][SP];     // P^T (keys x rows) for PV gemm
    float ms[BN];         // additive mask per key
};
// total: (64*132 + 64*132 + 128*68 + 128*132 + 128) * 4 = 170,496 bytes

__global__ __launch_bounds__(NT, 1)
void flash_attn_f32x2(const float* __restrict__ Q,
                      const float* __restrict__ K,
                      const float* __restrict__ V,
                      const float* __restrict__ mask,
                      float* __restrict__ out)
{
    extern __shared__ float smem_raw[];
    SmemT* s = reinterpret_cast<SmemT*>(smem_raw);

    const int tid = threadIdx.x;
    const int tx  = tid & 15;        // QK: key-col group (x8). PV: d-col group (x4).
    const int ty  = tid >> 4;        // query row group (x8)
    const int bh  = blockIdx.y;      // 0..63
    const int b   = bh >> 4;         // H = 16
    const long base = (long)bh * SEQ * DH;
    const int q0  = blockIdx.x * BM;

    const float* Qg = Q + base + (long)q0 * DH;
    const float* mrow = mask + (long)b * SEQ;

    // ---- Load Q tile transposed into smem, scaled by 1/8 = 1/sqrt(D) ----
    // (q/D^0.25)*(k/D^0.25) == (q*k)/8; fold whole factor into Q.
    #pragma unroll
    for (int i = 0; i < (BM * DH) / (4 * NT); ++i) {   // 8 float4 per thread
        int idx = tid + i * NT;
        int row = idx >> 4;
        int d4  = (idx & 15) << 2;
        float4 v = *reinterpret_cast<const float4*>(Qg + row * DH + d4);
        s->Qs[d4 + 0][row] = v.x * 0.125f;
        s->Qs[d4 + 1][row] = v.y * 0.125f;
        s->Qs[d4 + 2][row] = v.z * 0.125f;
        s->Qs[d4 + 3][row] = v.w * 0.125f;
    }

    // Per-thread output state: 8 rows x 4 d-cols (2 packed pairs), softmax m/l.
    ull Op[8][2];
    float m[8], l[8];
    #pragma unroll
    for (int i = 0; i < 8; ++i) {
        m[i] = -1e30f;
        l[i] = 0.0f;
        Op[i][0] = 0ull;
        Op[i][1] = 0ull;
    }

    for (int k0 = 0; k0 < SEQ; k0 += BN) {
        __syncthreads();   // previous PV reads of Ps/Vs done before overwrite

        // ---- Load K tile (transposed) + V tile + mask ----
        const float* Kg = K + base + (long)k0 * DH;
        const float* Vg = V + base + (long)k0 * DH;
        #pragma unroll
        for (int i = 0; i < (BN * DH) / (4 * NT); ++i) {
            int idx = tid + i * NT;
            int row = idx >> 4;
            int d4  = (idx & 15) << 2;
            float4 v = *reinterpret_cast<const float4*>(Kg + row * DH + d4);
            s->Ks[d4 + 0][row] = v.x;
            s->Ks[d4 + 1][row] = v.y;
            s->Ks[d4 + 2][row] = v.z;
            s->Ks[d4 + 3][row] = v.w;
            float4 w = *reinterpret_cast<const float4*>(Vg + row * DH + d4);
            *reinterpret_cast<float4*>(&s->Vs[row][d4]) = w;
        }
        if (tid < BN) s->ms[tid] = -1000.0f * (1.0f - mrow[k0 + tid]);
        __syncthreads();

        // ---- S = (Q/8) K^T : 8 rows x 8 keys (4 packed pairs), FFMA2 over d ----
        ull Cp[8][4];
        #pragma unroll
        for (int i = 0; i < 8; ++i)
            #pragma unroll
            for (int jp = 0; jp < 4; ++jp) Cp[i][jp] = 0ull;

        #pragma unroll 4
        for (int d = 0; d < DH; ++d) {
            float4 qa = *reinterpret_cast<const float4*>(&s->Qs[d][ty * 8]);
            float4 qb = *reinterpret_cast<const float4*>(&s->Qs[d][ty * 8 + 4]);
            ulonglong2 kA = *reinterpret_cast<const ulonglong2*>(&s->Ks[d][tx * 8]);
            ulonglong2 kB = *reinterpret_cast<const ulonglong2*>(&s->Ks[d][tx * 8 + 4]);
            ull bp[4] = {kA.x, kA.y, kB.x, kB.y};
            ull aa[8];
            PACKDUP(aa[0], qa.x); PACKDUP(aa[1], qa.y);
            PACKDUP(aa[2], qa.z); PACKDUP(aa[3], qa.w);
            PACKDUP(aa[4], qb.x); PACKDUP(aa[5], qb.y);
            PACKDUP(aa[6], qb.z); PACKDUP(aa[7], qb.w);
            #pragma unroll
            for (int i = 0; i < 8; ++i)
                #pragma unroll
                for (int jp = 0; jp < 4; ++jp)
                    FMA2(Cp[i][jp], aa[i], bp[jp], Cp[i][jp]);
        }

        // ---- additive mask (packed) ----
        {
            ulonglong2 mA = *reinterpret_cast<const ulonglong2*>(&s->ms[tx * 8]);
            ulonglong2 mB = *reinterpret_cast<const ulonglong2*>(&s->ms[tx * 8 + 4]);
            ull mp[4] = {mA.x, mA.y, mB.x, mB.y};
            #pragma unroll
            for (int i = 0; i < 8; ++i)
                #pragma unroll
                for (int jp = 0; jp < 4; ++jp)
                    ADD2(Cp[i][jp], Cp[i][jp], mp[jp]);
        }

        // ---- online softmax (scalar; row reduction over the 16 tx lanes) ----
        // Threads with equal ty are 16 contiguous lanes; xor offsets 8,4,2,1
        // stay inside that 16-lane group.
        #pragma unroll
        for (int i = 0; i < 8; ++i) {
            float C[8];
            #pragma unroll
            for (int jp = 0; jp < 4; ++jp)
                UNPACK2(C[2 * jp], C[2 * jp + 1], Cp[i][jp]);

            float rmax = C[0];
            #pragma unroll
            for (int j = 1; j < 8; ++j) rmax = fmaxf(rmax, C[j]);
            #pragma unroll
            for (int o = 8; o >= 1; o >>= 1)
                rmax = fmaxf(rmax, __shfl_xor_sync(0xffffffffu, rmax, o));

            float mn   = fmaxf(m[i], rmax);
            float corr = __expf(m[i] - mn);
            m[i] = mn;

            float rsum = 0.0f;
            #pragma unroll
            for (int j = 0; j < 8; ++j) {
                C[j] = __expf(C[j] - mn);
                rsum += C[j];
            }
            #pragma unroll
            for (int o = 8; o >= 1; o >>= 1)
                rsum += __shfl_xor_sync(0xffffffffu, rsum, o);

            l[i] = l[i] * corr + rsum;

            ull corrp;
            PACKDUP(corrp, corr);
            MUL2(Op[i][0], Op[i][0], corrp);
            MUL2(Op[i][1], Op[i][1], corrp);

            // stage probs back into Cp for the transpose below
            #pragma unroll
            for (int jp = 0; jp < 4; ++jp)
                PACK2(Cp[i][jp], C[2 * jp], C[2 * jp + 1]);
        }

        // ---- stage P transposed ([key][row]) for the PV gemm ----
        #pragma unroll
        for (int jp = 0; jp < 4; ++jp) {
            float c0[8], c1[8];   // key-cols 2jp, 2jp+1 across the 8 rows
            #pragma unroll
            for (int i = 0; i < 8; ++i) UNPACK2(c0[i], c1[i], Cp[i][jp]);
            float4 p00 = make_float4(c0[0], c0[1], c0[2], c0[3]);
            float4 p01 = make_float4(c0[4], c0[5], c0[6], c0[7]);
            float4 p10 = make_float4(c1[0], c1[1], c1[2], c1[3]);
            float4 p11 = make_float4(c1[4], c1[5], c1[6], c1[7]);
            *reinterpret_cast<float4*>(&s->Ps[tx * 8 + 2 * jp][ty * 8])         = p00;
            *reinterpret_cast<float4*>(&s->Ps[tx * 8 + 2 * jp][ty * 8 + 4])     = p01;
            *reinterpret_cast<float4*>(&s->Ps[tx * 8 + 2 * jp + 1][ty * 8])     = p10;
            *reinterpret_cast<float4*>(&s->Ps[tx * 8 + 2 * jp + 1][ty * 8 + 4]) = p11;
        }
        __syncthreads();

        // ---- O += P V : 8 rows x 4 d-cols per thread (cols = tx*4..tx*4+3) ----
        #pragma unroll 4
        for (int k = 0; k < BN; ++k) {
            float4 pa = *reinterpret_cast<const float4*>(&s->Ps[k][ty * 8]);
            float4 pb = *reinterpret_cast<const float4*>(&s->Ps[k][ty * 8 + 4]);
            ulonglong2 vp = *reinterpret_cast<const ulonglong2*>(&s->Vs[k][tx * 4]);
            ull aa[8];
            PACKDUP(aa[0], pa.x); PACKDUP(aa[1], pa.y);
            PACKDUP(aa[2], pa.z); PACKDUP(aa[3], pa.w);
            PACKDUP(aa[4], pb.x); PACKDUP(aa[5], pb.y);
            PACKDUP(aa[6], pb.z); PACKDUP(aa[7], pb.w);
            #pragma unroll
            for (int i = 0; i < 8; ++i) {
                FMA2(Op[i][0], aa[i], vp.x, Op[i][0]);
                FMA2(Op[i][1], aa[i], vp.y, Op[i][1]);
            }
        }
    }

    // ---- normalize (packed) and store: rows ty*8+i, cols tx*4..tx*4+3 ----
    float* Og = out + base + (long)q0 * DH;
    #pragma unroll
    for (int i = 0; i < 8; ++i) {
        float inv = 1.0f / l[i];
        ull invp;
        PACKDUP(invp, inv);
        ulonglong2 w;
        MUL2(w.x, Op[i][0], invp);
        MUL2(w.y, Op[i][1], invp);
        int row = ty * 8 + i;
        *reinterpret_cast<ulonglong2*>(Og + row * DH + tx * 4) = w;
    }
}

extern "C" void kernel_launch(void* const* d_in, const int* in_sizes, int n_in,
                              void* d_out, int out_size)
{
    const float* Q = (const float*)d_in[0];
    const float* K = (const float*)d_in[1];
    const float* V = (const float*)d_in[2];
    const float* M = (const float*)d_in[3];
    float* out = (float*)d_out;

    const size_t smem_bytes = sizeof(SmemT);   // 170,496 B
    cudaFuncSetAttribute(flash_attn_f32x2,
                         cudaFuncAttributeMaxDynamicSharedMemorySize,
                         (int)smem_bytes);

    dim3 grid(SEQ / BM, BATCH * HEADS);        // (16, 64) = 1024 CTAs
    flash_attn_f32x2<<<grid, NT, smem_bytes>>>(Q, K, V, M, out);
}

// round 8
// speedup vs baseline: 4.3645x; 4.3645x over previous
#include <cuda_runtime.h>
#include <cuda_bf16.h>
#include <cstdint>

// Shape: B=4, H=16, S=2048, D=64, fp32 in/out.
#define SEQ 2048
#define DH 64
#define BM 128
#define BN 64
#define NT 256
#define NTILES (SEQ / BN)
#define LDB 72   // bf16 elems per smem row (64 + 8 pad -> conflict-free ldmatrix)

// smem byte offsets
#define QHI 0
#define QLO (QHI + BM * LDB * 2)          // 18432
#define KHI (QLO + BM * LDB * 2)          // 36864
#define KLO (KHI + BN * LDB * 2)          // 46080
#define VHI (KLO + BN * LDB * 2)          // 55296
#define VLO (VHI + BN * LDB * 2)          // 64512
#define MSO (VLO + BN * LDB * 2)          // 73728
#define SM_TOTAL (MSO + BN * 4)           // 73984

__device__ __forceinline__ uint32_t smem_u32(const void* p) {
    uint32_t a;
    asm("{ .reg .u64 t; cvta.to.shared.u64 t, %1; cvt.u32.u64 %0, t; }" : "=r"(a) : "l"(p));
    return a;
}
__device__ __forceinline__ void ldsm_x4(uint32_t* r, uint32_t a) {
    asm volatile("ldmatrix.sync.aligned.m8n8.x4.shared.b16 {%0,%1,%2,%3}, [%4];"
                 : "=r"(r[0]), "=r"(r[1]), "=r"(r[2]), "=r"(r[3]) : "r"(a));
}
__device__ __forceinline__ void ldsm_x4_t(uint32_t* r, uint32_t a) {
    asm volatile("ldmatrix.sync.aligned.m8n8.x4.trans.shared.b16 {%0,%1,%2,%3}, [%4];"
                 : "=r"(r[0]), "=r"(r[1]), "=r"(r[2]), "=r"(r[3]) : "r"(a));
}
// D += A * B  (m16n8k16, bf16 in, fp32 accum)
__device__ __forceinline__ void mma16816(float* d, const uint32_t* a, uint32_t b0, uint32_t b1) {
    asm volatile("mma.sync.aligned.m16n8k16.row.col.f32.bf16.bf16.f32 "
                 "{%0,%1,%2,%3}, {%4,%5,%6,%7}, {%8,%9}, {%0,%1,%2,%3};"
                 : "+f"(d[0]), "+f"(d[1]), "+f"(d[2]), "+f"(d[3])
                 : "r"(a[0]), "r"(a[1]), "r"(a[2]), "r"(a[3]), "r"(b0), "r"(b1));
}

__device__ __forceinline__ uint32_t packbf(__nv_bfloat16 a, __nv_bfloat16 b) {
    return (uint32_t)__bfloat16_as_ushort(a) | ((uint32_t)__bfloat16_as_ushort(b) << 16);
}
// split pair (a,b) into packed bf16 hi and lo (residual) words
__device__ __forceinline__ void splitpack(float a, float b, uint32_t& hi, uint32_t& lo) {
    __nv_bfloat16 ha = __float2bfloat16(a), hb = __float2bfloat16(b);
    hi = packbf(ha, hb);
    lo = packbf(__float2bfloat16(a - __bfloat162float(ha)),
                __float2bfloat16(b - __bfloat162float(hb)));
}

__global__ __launch_bounds__(NT, 2)
void flash_attn_hmma(const float* __restrict__ Q, const float* __restrict__ K,
                     const float* __restrict__ V, const float* __restrict__ mask,
                     float* __restrict__ out)
{
    extern __shared__ char sm[];
    const uint32_t smb = smem_u32(sm);
    const int tid  = threadIdx.x;
    const int warp = tid >> 5;
    const int lane = tid & 31;
    const int bh = blockIdx.y;
    const int b  = bh >> 4;
    const long base = (long)bh * SEQ * DH;
    const int q0 = blockIdx.x * BM;
    const float* mrow = mask + (long)b * SEQ;

    // ---- load Q [128][64], scale by 1/8 (= 1/sqrt(64), folds both D^0.25), split ----
    {
        const float* Qg = Q + base + (long)q0 * DH;
        #pragma unroll
        for (int i = 0; i < 8; ++i) {
            int idx = tid + i * NT;
            int row = idx >> 4;
            int c4  = (idx & 15) << 2;
            float4 v = *reinterpret_cast<const float4*>(Qg + row * DH + c4);
            uint32_t h0, l0, h1, l1;
            splitpack(v.x * 0.125f, v.y * 0.125f, h0, l0);
            splitpack(v.z * 0.125f, v.w * 0.125f, h1, l1);
            int off = (row * LDB + c4) * 2;
            *reinterpret_cast<uint2*>(sm + QHI + off) = make_uint2(h0, h1);
            *reinterpret_cast<uint2*>(sm + QLO + off) = make_uint2(l0, l1);
        }
    }

    float O[8][4];
    #pragma unroll
    for (int i = 0; i < 8; ++i)
        #pragma unroll
        for (int j = 0; j < 4; ++j) O[i][j] = 0.0f;
    float ml0 = -1e30f, ml1 = -1e30f, ls0 = 0.0f, ls1 = 0.0f;

    const int cb = 2 * (lane & 3);          // accum col base within an 8-wide tile
    const float* msp = reinterpret_cast<const float*>(sm + MSO);
    const int g  = lane >> 3, lr = lane & 7;

    for (int t = 0; t < NTILES; ++t) {
        __syncthreads();   // prior tile's ldmatrix reads done before overwrite
        // ---- load K,V tiles [64][64], split; mask ----
        {
            const float* Kg = K + base + (long)t * BN * DH;
            const float* Vg = V + base + (long)t * BN * DH;
            #pragma unroll
            for (int i = 0; i < 4; ++i) {
                int idx = tid + i * NT;
                int row = idx >> 4;
                int c4  = (idx & 15) << 2;
                int off = (row * LDB + c4) * 2;
                float4 v = *reinterpret_cast<const float4*>(Kg + row * DH + c4);
                uint32_t h0, l0, h1, l1;
                splitpack(v.x, v.y, h0, l0);
                splitpack(v.z, v.w, h1, l1);
                *reinterpret_cast<uint2*>(sm + KHI + off) = make_uint2(h0, h1);
                *reinterpret_cast<uint2*>(sm + KLO + off) = make_uint2(l0, l1);
                float4 w = *reinterpret_cast<const float4*>(Vg + row * DH + c4);
                splitpack(w.x, w.y, h0, l0);
                splitpack(w.z, w.w, h1, l1);
                *reinterpret_cast<uint2*>(sm + VHI + off) = make_uint2(h0, h1);
                *reinterpret_cast<uint2*>(sm + VLO + off) = make_uint2(l0, l1);
            }
            if (tid < BN)
                reinterpret_cast<float*>(sm + MSO)[tid] = -1000.0f * (1.0f - mrow[t * BN + tid]);
        }
        __syncthreads();

        // ---- S = Q K^T : 8 n-tiles of 16x8, split bf16 (hh + hl + lh) ----
        float S[8][4];
        #pragma unroll
        for (int i = 0; i < 8; ++i)
            #pragma unroll
            for (int j = 0; j < 4; ++j) S[i][j] = 0.0f;

        #pragma unroll
        for (int kt = 0; kt < 4; ++kt) {
            uint32_t ah[4], al[4];
            uint32_t aaddr = smb + QHI +
                (uint32_t)(((warp * 16 + (lane & 15)) * LDB + kt * 16 + (lane >> 4) * 8) * 2);
            ldsm_x4(ah, aaddr);
            ldsm_x4(al, aaddr + (QLO - QHI));
            #pragma unroll
            for (int np = 0; np < 4; ++np) {
                int key = np * 16 + ((g & 2) ? 8 : 0) + lr;
                int col = kt * 16 + ((g & 1) ? 8 : 0);
                uint32_t baddr = smb + KHI + (uint32_t)((key * LDB + col) * 2);
                uint32_t bh4[4], bl4[4];
                ldsm_x4(bh4, baddr);
                ldsm_x4(bl4, baddr + (KLO - KHI));
                mma16816(S[2*np],   ah, bh4[0], bh4[1]);
                mma16816(S[2*np],   ah, bl4[0], bl4[1]);
                mma16816(S[2*np],   al, bh4[0], bh4[1]);
                mma16816(S[2*np+1], ah, bh4[2], bh4[3]);
                mma16816(S[2*np+1], ah, bl4[2], bl4[3]);
                mma16816(S[2*np+1], al, bh4[2], bh4[3]);
            }
        }

        // ---- mask + online softmax (rows r0=lane>>2 and r0+8; 4-lane shfl groups) ----
        float mo0 = ml0, mo1 = ml1;
        float mx0 = ml0, mx1 = ml1;
        #pragma unroll
        for (int nt = 0; nt < 8; ++nt) {
            float k0m = msp[nt * 8 + cb], k1m = msp[nt * 8 + cb + 1];
            S[nt][0] += k0m; S[nt][1] += k1m;
            S[nt][2] += k0m; S[nt][3] += k1m;
            mx0 = fmaxf(mx0, fmaxf(S[nt][0], S[nt][1]));
            mx1 = fmaxf(mx1, fmaxf(S[nt][2], S[nt][3]));
        }
        mx0 = fmaxf(mx0, __shfl_xor_sync(0xffffffffu, mx0, 1));
        mx0 = fmaxf(mx0, __shfl_xor_sync(0xffffffffu, mx0, 2));
        mx1 = fmaxf(mx1, __shfl_xor_sync(0xffffffffu, mx1, 1));
        mx1 = fmaxf(mx1, __shfl_xor_sync(0xffffffffu, mx1, 2));
        float corr0 = __expf(mo0 - mx0), corr1 = __expf(mo1 - mx1);
        ml0 = mx0; ml1 = mx1;
        float rs0 = 0.0f, rs1 = 0.0f;
        #pragma unroll
        for (int nt = 0; nt < 8; ++nt) {
            S[nt][0] = __expf(S[nt][0] - mx0);
            S[nt][1] = __expf(S[nt][1] - mx0);
            S[nt][2] = __expf(S[nt][2] - mx1);
            S[nt][3] = __expf(S[nt][3] - mx1);
            rs0 += S[nt][0] + S[nt][1];
            rs1 += S[nt][2] + S[nt][3];
        }
        rs0 += __shfl_xor_sync(0xffffffffu, rs0, 1);
        rs0 += __shfl_xor_sync(0xffffffffu, rs0, 2);
        rs1 += __shfl_xor_sync(0xffffffffu, rs1, 1);
        rs1 += __shfl_xor_sync(0xffffffffu, rs1, 2);
        ls0 = ls0 * corr0 + rs0;
        ls1 = ls1 * corr1 + rs1;
        #pragma unroll
        for (int nt = 0; nt < 8; ++nt) {
            O[nt][0] *= corr0; O[nt][1] *= corr0;
            O[nt][2] *= corr1; O[nt][3] *= corr1;
        }

        // ---- O += P V : P from registers (S-accum layout == A-frag layout) ----
        #pragma unroll
        for (int kt = 0; kt < 4; ++kt) {
            uint32_t ph[4], pl[4];
            splitpack(S[2*kt][0],   S[2*kt][1],   ph[0], pl[0]);
            splitpack(S[2*kt][2],   S[2*kt][3],   ph[1], pl[1]);
            splitpack(S[2*kt+1][0], S[2*kt+1][1], ph[2], pl[2]);
            splitpack(S[2*kt+1][2], S[2*kt+1][3], ph[3], pl[3]);
            #pragma unroll
            for (int dp = 0; dp < 4; ++dp) {
                int key = kt * 16 + ((g & 1) ? 8 : 0) + lr;
                int col = dp * 16 + ((g & 2) ? 8 : 0);
                uint32_t vaddr = smb + VHI + (uint32_t)((key * LDB + col) * 2);
                uint32_t vh4[4], vl4[4];
                ldsm_x4_t(vh4, vaddr);
                ldsm_x4_t(vl4, vaddr + (VLO - VHI));
                mma16816(O[2*dp],   ph, vh4[0], vh4[1]);
                mma16816(O[2*dp],   ph, vl4[0], vl4[1]);
                mma16816(O[2*dp],   pl, vh4[0], vh4[1]);
                mma16816(O[2*dp+1], ph, vh4[2], vh4[3]);
                mma16816(O[2*dp+1], ph, vl4[2], vl4[3]);
                mma16816(O[2*dp+1], pl, vh4[2], vh4[3]);
            }
        }
    }

    // ---- epilogue: O / l, fp32 store ----
    float inv0 = 1.0f / ls0, inv1 = 1.0f / ls1;
    const int r0 = lane >> 2;
    float* Og = out + base + (long)(q0 + warp * 16) * DH;
    #pragma unroll
    for (int nt = 0; nt < 8; ++nt) {
        float2 w0 = make_float2(O[nt][0] * inv0, O[nt][1] * inv0);
        float2 w1 = make_float2(O[nt][2] * inv1, O[nt][3] * inv1);
        *reinterpret_cast<float2*>(Og + (long)r0 * DH       + nt * 8 + cb) = w0;
        *reinterpret_cast<float2*>(Og + (long)(r0 + 8) * DH + nt * 8 + cb) = w1;
    }
}

extern "C" void kernel_launch(void* const* d_in, const int* in_sizes, int n_in,
                              void* d_out, int out_size)
{
    const float* Q = (const float*)d_in[0];
    const float* K = (const float*)d_in[1];
    const float* V = (const float*)d_in[2];
    const float* M = (const float*)d_in[3];
    float* out = (float*)d_out;

    cudaFuncSetAttribute(flash_attn_hmma,
                         cudaFuncAttributeMaxDynamicSharedMemorySize, SM_TOTAL);

    dim3 grid(SEQ / BM, 4 * 16);   // (16, 64) = 1024 CTAs
    flash_attn_hmma<<<grid, NT, SM_TOTAL>>>(Q, K, V, M, out);
}

// round 13
// speedup vs baseline: 5.1518x; 1.1804x over previous
#include <cuda_runtime.h>
#include <cuda_bf16.h>
#include <cstdint>

// Shape: B=4, H=16, S=2048, D=64, fp32 in/out.
#define SEQ 2048
#define DH 64
#define BM 128
#define BN 64
#define NT 256
#define NTILES (SEQ / BN)
#define LDB 72          // Q smem row pitch in bf16 (64 + 8 pad)
#define NBH 64
#define KVELEMS (NBH * SEQ * DH)   // 8,388,608

// ---- device-global scratch: pre-split bf16 hi/lo for K and V ----
__device__ __align__(16) uint4 g_khi[KVELEMS / 8];
__device__ __align__(16) uint4 g_klo[KVELEMS / 8];
__device__ __align__(16) uint4 g_vhi[KVELEMS / 8];
__device__ __align__(16) uint4 g_vlo[KVELEMS / 8];

// ---- smem layout (bytes) ----
#define QHI 0
#define QLO 18432
#define KVST 36864                 // stage s at KVST + s*32768
#define PKH 0
#define PKL 8192
#define PVH 16384
#define PVL 24576
#define MSK 102400                 // mask stage s at MSK + s*256
#define SM_TOTAL 102912

__device__ __forceinline__ uint32_t smem_u32(const void* p) {
    uint32_t a;
    asm("{ .reg .u64 t; cvta.to.shared.u64 t, %1; cvt.u32.u64 %0, t; }" : "=r"(a) : "l"(p));
    return a;
}
__device__ __forceinline__ void ldsm_x4(uint32_t* r, uint32_t a) {
    asm volatile("ldmatrix.sync.aligned.m8n8.x4.shared.b16 {%0,%1,%2,%3}, [%4];"
                 : "=r"(r[0]), "=r"(r[1]), "=r"(r[2]), "=r"(r[3]) : "r"(a));
}
__device__ __forceinline__ void ldsm_x4_t(uint32_t* r, uint32_t a) {
    asm volatile("ldmatrix.sync.aligned.m8n8.x4.trans.shared.b16 {%0,%1,%2,%3}, [%4];"
                 : "=r"(r[0]), "=r"(r[1]), "=r"(r[2]), "=r"(r[3]) : "r"(a));
}
__device__ __forceinline__ void mma16816(float* d, const uint32_t* a, uint32_t b0, uint32_t b1) {
    asm volatile("mma.sync.aligned.m16n8k16.row.col.f32.bf16.bf16.f32 "
                 "{%0,%1,%2,%3}, {%4,%5,%6,%7}, {%8,%9}, {%0,%1,%2,%3};"
                 : "+f"(d[0]), "+f"(d[1]), "+f"(d[2]), "+f"(d[3])
                 : "r"(a[0]), "r"(a[1]), "r"(a[2]), "r"(a[3]), "r"(b0), "r"(b1));
}
__device__ __forceinline__ uint32_t packbf(__nv_bfloat16 a, __nv_bfloat16 b) {
    return (uint32_t)__bfloat16_as_ushort(a) | ((uint32_t)__bfloat16_as_ushort(b) << 16);
}
__device__ __forceinline__ void splitpack(float a, float b, uint32_t& hi, uint32_t& lo) {
    __nv_bfloat16 ha = __float2bfloat16(a), hb = __float2bfloat16(b);
    hi = packbf(ha, hb);
    lo = packbf(__float2bfloat16(a - __bfloat162float(ha)),
                __float2bfloat16(b - __bfloat162float(hb)));
}
#define CP_ASYNC16(dst, src) \
    asm volatile("cp.async.cg.shared.global [%0], [%1], 16;" :: "r"(dst), "l"(src))
#define CP_COMMIT() asm volatile("cp.async.commit_group;" ::: "memory")
#define CP_WAIT0()  asm volatile("cp.async.wait_group 0;" ::: "memory")

// ---- pre-pass: split K,V fp32 -> bf16 hi/lo ----
__global__ __launch_bounds__(256)
void presplit(const float4* __restrict__ K, const float4* __restrict__ V)
{
    int i = blockIdx.x * blockDim.x + threadIdx.x;   // over KVELEMS/4 float4s
    float4 k = K[i];
    uint32_t h0, l0, h1, l1;
    splitpack(k.x, k.y, h0, l0);
    splitpack(k.z, k.w, h1, l1);
    reinterpret_cast<uint2*>(g_khi)[i] = make_uint2(h0, h1);
    reinterpret_cast<uint2*>(g_klo)[i] = make_uint2(l0, l1);
    float4 v = V[i];
    splitpack(v.x, v.y, h0, l0);
    splitpack(v.z, v.w, h1, l1);
    reinterpret_cast<uint2*>(g_vhi)[i] = make_uint2(h0, h1);
    reinterpret_cast<uint2*>(g_vlo)[i] = make_uint2(l0, l1);
}

// issue cp.async for one K/V tile into stage (8 chunks of 16B per thread)
__device__ __forceinline__ void issue_kv(uint32_t smb, int stage, int t, int bh)
{
    const int tid = threadIdx.x;
    const int r  = tid >> 3;        // 0..31
    const int ch = tid & 7;         // 16B chunk within 128B row
    const long cb = (long)bh * (SEQ * DH / 8) + (long)t * (BN * DH / 8);
    const uint32_t sb = smb + KVST + stage * 32768;
    #pragma unroll
    for (int j = 0; j < 8; ++j) {
        const int part = j >> 1;                  // 0:KH 1:KL 2:VH 3:VL
        const int row  = (j & 1) * 32 + r;        // 0..63
        const uint4* gp = (part == 0) ? g_khi : (part == 1) ? g_klo
                        : (part == 2) ? g_vhi : g_vlo;
        const uint4* src = gp + cb + row * (DH / 8) + ch;
        uint32_t dst = sb + part * 8192 + row * 128 + ((ch ^ (row & 7)) << 4);
        CP_ASYNC16(dst, src);
    }
}

__global__ __launch_bounds__(NT, 2)
void flash_attn_hmma(const float* __restrict__ Q, const float* __restrict__ mask,
                     float* __restrict__ out)
{
    extern __shared__ char sm[];
    const uint32_t smb = smem_u32(sm);
    const int tid  = threadIdx.x;
    const int warp = tid >> 5;
    const int lane = tid & 31;
    const int bh = blockIdx.y;
    const int b  = bh >> 4;
    const long base = (long)bh * SEQ * DH;
    const int q0 = blockIdx.x * BM;
    const float* mrow = mask + (long)b * SEQ;

    // prefetch tile 0 ASAP
    issue_kv(smb, 0, 0, bh);
    CP_COMMIT();
    if (tid < BN)
        reinterpret_cast<float*>(sm + MSK)[tid] = -1000.0f * (1.0f - mrow[tid]);

    // ---- load Q [128][64], scale by 1/8 (= 1/sqrt(64)), split, padded rows ----
    {
        const float* Qg = Q + base + (long)q0 * DH;
        #pragma unroll
        for (int i = 0; i < 8; ++i) {
            int idx = tid + i * NT;
            int row = idx >> 4;
            int c4  = (idx & 15) << 2;
            float4 v = *reinterpret_cast<const float4*>(Qg + row * DH + c4);
            uint32_t h0, l0, h1, l1;
            splitpack(v.x * 0.125f, v.y * 0.125f, h0, l0);
            splitpack(v.z * 0.125f, v.w * 0.125f, h1, l1);
            int off = (row * LDB + c4) * 2;
            *reinterpret_cast<uint2*>(sm + QHI + off) = make_uint2(h0, h1);
            *reinterpret_cast<uint2*>(sm + QLO + off) = make_uint2(l0, l1);
        }
    }

    float O[8][4];
    #pragma unroll
    for (int i = 0; i < 8; ++i)
        #pragma unroll
        for (int j = 0; j < 4; ++j) O[i][j] = 0.0f;
    float ml0 = -1e30f, ml1 = -1e30f, ls0 = 0.0f, ls1 = 0.0f;

    const int cb2 = 2 * (lane & 3);
    const int g  = lane >> 3, lr = lane & 7;

    for (int t = 0; t < NTILES; ++t) {
        CP_WAIT0();          // stage t&1 data landed (this thread's copies)
        __syncthreads();     // ...and visible to all; prior tile reads done

        // prefetch tile t+1 into the other stage (overwrites stage read 2 tiles ago)
        if (t + 1 < NTILES) {
            issue_kv(smb, (t + 1) & 1, t + 1, bh);
            CP_COMMIT();
            if (tid < BN)
                reinterpret_cast<float*>(sm + MSK + ((t + 1) & 1) * 256)[tid] =
                    -1000.0f * (1.0f - mrow[(t + 1) * BN + tid]);
        } else {
            CP_COMMIT();     // keep group count in sync for final WAIT0
        }

        const uint32_t stb = smb + KVST + (t & 1) * 32768;
        const float* msp = reinterpret_cast<const float*>(sm + MSK + (t & 1) * 256);

        // ---- S = Q K^T : split bf16 (hh + hl + lh) ----
        float S[8][4];
        #pragma unroll
        for (int i = 0; i < 8; ++i)
            #pragma unroll
            for (int j = 0; j < 4; ++j) S[i][j] = 0.0f;

        #pragma unroll
        for (int kt = 0; kt < 4; ++kt) {
            uint32_t ah[4], al[4];
            uint32_t aaddr = smb + QHI +
                (uint32_t)(((warp * 16 + (lane & 15)) * LDB + kt * 16 + (lane >> 4) * 8) * 2);
            ldsm_x4(ah, aaddr);
            ldsm_x4(al, aaddr + (QLO - QHI));
            #pragma unroll
            for (int np = 0; np < 4; ++np) {
                int key = np * 16 + ((g & 2) ? 8 : 0) + lr;
                int chk = kt * 2 + (g & 1);
                uint32_t baddr = stb + PKH + key * 128 + ((chk ^ (key & 7)) << 4);
                uint32_t bh4[4], bl4[4];
                ldsm_x4(bh4, baddr);
                ldsm_x4(bl4, baddr + (PKL - PKH));
                mma16816(S[2*np],   ah, bh4[0], bh4[1]);
                mma16816(S[2*np],   ah, bl4[0], bl4[1]);
                mma16816(S[2*np],   al, bh4[0], bh4[1]);
                mma16816(S[2*np+1], ah, bh4[2], bh4[3]);
                mma16816(S[2*np+1], ah, bl4[2], bl4[3]);
                mma16816(S[2*np+1], al, bh4[2], bh4[3]);
            }
        }

        // ---- mask + online softmax (rows lane>>2 and +8; 4-lane shfl groups) ----
        float mo0 = ml0, mo1 = ml1;
        float mx0 = ml0, mx1 = ml1;
        #pragma unroll
        for (int nt = 0; nt < 8; ++nt) {
            float k0m = msp[nt * 8 + cb2], k1m = msp[nt * 8 + cb2 + 1];
            S[nt][0] += k0m; S[nt][1] += k1m;
            S[nt][2] += k0m; S[nt][3] += k1m;
            mx0 = fmaxf(mx0, fmaxf(S[nt][0], S[nt][1]));
            mx1 = fmaxf(mx1, fmaxf(S[nt][2], S[nt][3]));
        }
        mx0 = fmaxf(mx0, __shfl_xor_sync(0xffffffffu, mx0, 1));
        mx0 = fmaxf(mx0, __shfl_xor_sync(0xffffffffu, mx0, 2));
        mx1 = fmaxf(mx1, __shfl_xor_sync(0xffffffffu, mx1, 1));
        mx1 = fmaxf(mx1, __shfl_xor_sync(0xffffffffu, mx1, 2));
        float corr0 = __expf(mo0 - mx0), corr1 = __expf(mo1 - mx1);
        ml0 = mx0; ml1 = mx1;
        float rs0 = 0.0f, rs1 = 0.0f;
        #pragma unroll
        for (int nt = 0; nt < 8; ++nt) {
            S[nt][0] = __expf(S[nt][0] - mx0);
            S[nt][1] = __expf(S[nt][1] - mx0);
            S[nt][2] = __expf(S[nt][2] - mx1);
            S[nt][3] = __expf(S[nt][3] - mx1);
            rs0 += S[nt][0] + S[nt][1];
            rs1 += S[nt][2] + S[nt][3];
        }
        rs0 += __shfl_xor_sync(0xffffffffu, rs0, 1);
        rs0 += __shfl_xor_sync(0xffffffffu, rs0, 2);
        rs1 += __shfl_xor_sync(0xffffffffu, rs1, 1);
        rs1 += __shfl_xor_sync(0xffffffffu, rs1, 2);
        ls0 = ls0 * corr0 + rs0;
        ls1 = ls1 * corr1 + rs1;
        #pragma unroll
        for (int nt = 0; nt < 8; ++nt) {
            O[nt][0] *= corr0; O[nt][1] *= corr0;
            O[nt][2] *= corr1; O[nt][3] *= corr1;
        }

        // ---- O += P V : P from registers (S-accum layout == A-frag layout) ----
        #pragma unroll
        for (int kt = 0; kt < 4; ++kt) {
            uint32_t ph[4], pl[4];
            splitpack(S[2*kt][0],   S[2*kt][1],   ph[0], pl[0]);
            splitpack(S[2*kt][2],   S[2*kt][3],   ph[1], pl[1]);
            splitpack(S[2*kt+1][0], S[2*kt+1][1], ph[2], pl[2]);
            splitpack(S[2*kt+1][2], S[2*kt+1][3], ph[3], pl[3]);
            #pragma unroll
            for (int dp = 0; dp < 4; ++dp) {
                int key = kt * 16 + ((g & 1) ? 8 : 0) + lr;
                int chk = dp * 2 + ((g >> 1) & 1);
                uint32_t vaddr = stb + PVH + key * 128 + ((chk ^ (key & 7)) << 4);
                uint32_t vh4[4], vl4[4];
                ldsm_x4_t(vh4, vaddr);
                ldsm_x4_t(vl4, vaddr + (PVL - PVH));
                mma16816(O[2*dp],   ph, vh4[0], vh4[1]);
                mma16816(O[2*dp],   ph, vl4[0], vl4[1]);
                mma16816(O[2*dp],   pl, vh4[0], vh4[1]);
                mma16816(O[2*dp+1], ph, vh4[2], vh4[3]);
                mma16816(O[2*dp+1], ph, vl4[2], vl4[3]);
                mma16816(O[2*dp+1], pl, vh4[2], vh4[3]);
            }
        }
    }

    // ---- epilogue: O / l, fp32 store ----
    float inv0 = 1.0f / ls0, inv1 = 1.0f / ls1;
    const int r0 = lane >> 2;
    float* Og = out + base + (long)(q0 + warp * 16) * DH;
    #pragma unroll
    for (int nt = 0; nt < 8; ++nt) {
        float2 w0 = make_float2(O[nt][0] * inv0, O[nt][1] * inv0);
        float2 w1 = make_float2(O[nt][2] * inv1, O[nt][3] * inv1);
        *reinterpret_cast<float2*>(Og + (long)r0 * DH       + nt * 8 + cb2) = w0;
        *reinterpret_cast<float2*>(Og + (long)(r0 + 8) * DH + nt * 8 + cb2) = w1;
    }
}

extern "C" void kernel_launch(void* const* d_in, const int* in_sizes, int n_in,
                              void* d_out, int out_size)
{
    const float* Q = (const float*)d_in[0];
    const float* K = (const float*)d_in[1];
    const float* V = (const float*)d_in[2];
    const float* M = (const float*)d_in[3];
    float* out = (float*)d_out;

    presplit<<<KVELEMS / 4 / 256, 256>>>((const float4*)K, (const float4*)V);

    cudaFuncSetAttribute(flash_attn_hmma,
                         cudaFuncAttributeMaxDynamicSharedMemorySize, SM_TOTAL);
    dim3 grid(SEQ / BM, 4 * 16);   // (16, 64) = 1024 CTAs
    flash_attn_hmma<<<grid, NT, SM_TOTAL>>>(Q, M, out);
}